// round 1
// baseline (speedup 1.0000x reference)
#include <cuda_runtime.h>

#define NG 768
#define H  128
#define BT 64
#define TF4 16   // 64 floats = 16 float4 per k-row of a tile

// Precomputed, transposed operands: [k][gene] layout for coalesced+conflict-free tile fills.
__device__ float g_AiT[H * NG];  // (X @ W1[:, :H]^T + b1), transposed
__device__ float g_BjT[H * NG];  // (X @ W1[:, H:]^T), transposed
__device__ float g_YT [H * NG];  // (X @ Wb[0]), transposed
__device__ float g_XT [H * NG];  // X transposed

__global__ void prep_kernel(const float* __restrict__ X,
                            const float* __restrict__ W1,
                            const float* __restrict__ b1,
                            const float* __restrict__ Wb) {
    int i = blockIdx.x;      // gene row
    int m = blockIdx.y;      // which output matrix
    int t = threadIdx.x;     // hidden index
    __shared__ float xr[H];
    xr[t] = X[i * H + t];
    __syncthreads();

    float acc = 0.f;
    if (m == 0) {
        const float* w = W1 + t * (2 * H);
        #pragma unroll 8
        for (int k = 0; k < H; k++) acc = fmaf(xr[k], w[k], acc);
        g_AiT[t * NG + i] = acc + b1[t];
    } else if (m == 1) {
        const float* w = W1 + t * (2 * H) + H;
        #pragma unroll 8
        for (int k = 0; k < H; k++) acc = fmaf(xr[k], w[k], acc);
        g_BjT[t * NG + i] = acc;
    } else if (m == 2) {
        #pragma unroll 8
        for (int k = 0; k < H; k++) acc = fmaf(xr[k], Wb[k * H + t], acc);
        g_YT[t * NG + i] = acc;
    } else {
        g_XT[t * NG + i] = xr[t];
    }
}

__global__ __launch_bounds__(256, 1)
void pair_kernel(const float* __restrict__ W2,
                 const float* __restrict__ b2,
                 const float* __restrict__ bb,
                 float* __restrict__ out) {
    extern __shared__ float sm[];
    float4* As4 = (float4*)sm;           // [128][16] float4  (Ai'+b1, i-tile)
    float4* Bs4 = As4 + H * TF4;         // (Bj, j-tile)
    float4* Ys4 = Bs4 + H * TF4;         // (Y, i-tile)
    float4* Xs4 = Ys4 + H * TF4;         // (X, j-tile)
    float*  wd0 = (float*)(Xs4 + H * TF4);  // W2[0]-W2[1]
    float*  wd1 = wd0 + H;                  // W2[0]-W2[2]

    int tid = threadIdx.x;
    int bi = blockIdx.y, bj = blockIdx.x;
    int bi16 = bi * TF4, bj16 = bj * TF4;

    const float4* A  = (const float4*)g_AiT;
    const float4* B  = (const float4*)g_BjT;
    const float4* Yv = (const float4*)g_YT;
    const float4* Xv = (const float4*)g_XT;

    // Tile fill: idx = k*16 + c; gmem reads are 256B-contiguous per half warp,
    // smem writes are contiguous float4 — no transpose needed (done in prep).
    #pragma unroll
    for (int it = 0; it < 8; ++it) {
        int idx = tid + 256 * it;
        int k = idx >> 4, c = idx & 15;
        int so = k * (NG / 4);
        As4[idx] = A [so + bi16 + c];
        Bs4[idx] = B [so + bj16 + c];
        Ys4[idx] = Yv[so + bi16 + c];
        Xs4[idx] = Xv[so + bj16 + c];
    }
    if (tid < H) {
        float w0 = W2[tid], w1 = W2[H + tid], w2v = W2[2 * H + tid];
        wd0[tid] = w0 - w1;
        wd1[tid] = w0 - w2v;
    }
    __syncthreads();

    int tx = tid & 15, ty = tid >> 4;

    float a01[16], a02[16], aaf[16];
    #pragma unroll
    for (int r = 0; r < 16; r++) { a01[r] = 0.f; a02[r] = 0.f; aaf[r] = 0.f; }

    #pragma unroll 4
    for (int k = 0; k < H; k++) {
        float4 a = As4[k * TF4 + ty];
        float4 b = Bs4[k * TF4 + tx];
        float4 y = Ys4[k * TF4 + ty];
        float4 x = Xs4[k * TF4 + tx];
        float w0 = wd0[k], w1 = wd1[k];
        float av[4] = {a.x, a.y, a.z, a.w};
        float bv[4] = {b.x, b.y, b.z, b.w};
        float yv[4] = {y.x, y.y, y.z, y.w};
        float xv[4] = {x.x, x.y, x.z, x.w};
        #pragma unroll
        for (int p = 0; p < 4; p++) {
            #pragma unroll
            for (int q = 0; q < 4; q++) {
                int r = p * 4 + q;
                float h = fmaxf(av[p] + bv[q], 0.f);
                a01[r] = fmaf(h, w0, a01[r]);        // l0 - l1 accumulator
                a02[r] = fmaf(h, w1, a02[r]);        // l0 - l2 accumulator
                aaf[r] = fmaf(yv[p], xv[q], aaf[r]); // bilinear affinity
            }
        }
    }

    float db01 = b2[0] - b2[1];
    float db02 = b2[0] - b2[2];
    float bbv  = bb[0];

    #pragma unroll
    for (int p = 0; p < 4; p++) {
        int gi = bi * BT + ty * 4 + p;
        float ov[4];
        #pragma unroll
        for (int q = 0; q < 4; q++) {
            int r = p * 4 + q;
            float d01 = a01[r] + db01;   // l0 - l1
            float d02 = a02[r] + db02;   // l0 - l2
            float af  = aaf[r] + bbv;
            // argmax first-occurrence semantics:
            // cls==0 <=> l0>=l1 && l0>=l2 ; cls==2 <=> l2>l0 && l2>l1
            float s = (d01 >= 0.f && d02 >= 0.f) ? 1.f
                    : ((d02 < 0.f && d02 < d01) ? -1.f : 0.f);
            int gj = bj * BT + tx * 4 + q;
            ov[q] = (gi == gj) ? 0.f : s * af;
        }
        float4 o; o.x = ov[0]; o.y = ov[1]; o.z = ov[2]; o.w = ov[3];
        *(float4*)&out[gi * NG + bj * BT + tx * 4] = o;
    }
}

extern "C" void kernel_launch(void* const* d_in, const int* in_sizes, int n_in,
                              void* d_out, int out_size) {
    const float* X  = (const float*)d_in[0];
    const float* W1 = (const float*)d_in[1];
    const float* b1 = (const float*)d_in[2];
    const float* W2 = (const float*)d_in[3];
    const float* b2 = (const float*)d_in[4];
    const float* Wb = (const float*)d_in[5];
    const float* bb = (const float*)d_in[6];
    float* out = (float*)d_out;

    size_t smem = (size_t)(4 * H * TF4) * sizeof(float4) + 2 * H * sizeof(float);
    cudaFuncSetAttribute(pair_kernel, cudaFuncAttributeMaxDynamicSharedMemorySize,
                         (int)smem);

    prep_kernel<<<dim3(NG, 4), H>>>(X, W1, b1, Wb);
    pair_kernel<<<dim3(NG / BT, NG / BT), 256, smem>>>(W2, b2, bb, out);
}

// round 5
// speedup vs baseline: 3.3768x; 3.3768x over previous
#include <cuda_runtime.h>

#define NG 768
#define H  128
typedef unsigned long long ull;

// Prep outputs, all [k][gene]-major. i-side operands are pre-DUPLICATED
// ({v,v} pairs) so the pair kernel can load packed f32x2 operands directly.
__device__ float g_AiT_dup[H * 2 * NG];  // (X@W1a^T + b1), dup
__device__ float g_YT_dup [H * 2 * NG];  // (X@Wb), dup
__device__ float g_BjT[H * NG];          // (X@W1b^T)
__device__ float g_XT [H * NG];          // X^T

__device__ __forceinline__ ull relu2_add(ull a, ull b) {
    ull r;
    asm("{\n\t.reg .b64 t;\n\t.reg .f32 lo, hi;\n\t"
        "add.rn.f32x2 t, %1, %2;\n\t"
        "mov.b64 {lo, hi}, t;\n\t"
        "max.f32 lo, lo, 0f00000000;\n\t"
        "max.f32 hi, hi, 0f00000000;\n\t"
        "mov.b64 %0, {lo, hi};\n\t}"
        : "=l"(r) : "l"(a), "l"(b));
    return r;
}
__device__ __forceinline__ void fma2(ull& acc, ull a, ull b) {
    asm("fma.rn.f32x2 %0, %1, %2, %0;" : "+l"(acc) : "l"(a), "l"(b));
}

// Tiled prep GEMMs: grid (48, 3), 256 threads. 16-gene tile per block.
// m=0: Ai = X@W1[:, :H]^T + b1 -> g_AiT_dup ; m=1: Bj = X@W1[:, H:]^T -> g_BjT (+ X^T)
// m=2: Y = X@Wb -> g_YT_dup
__global__ __launch_bounds__(256)
void prep_gemm(const float* __restrict__ X, const float* __restrict__ W1,
               const float* __restrict__ b1, const float* __restrict__ Wb) {
    extern __shared__ float psm[];
    float* Ws = psm;               // [128][132] padded, Ws[t][k]
    float* Xs = psm + 128 * 132;   // [16][128]
    float4* Xs4 = (float4*)Xs;

    int tid = threadIdx.x;
    int m = blockIdx.y;
    int g0 = blockIdx.x * 16;

    if (m < 2) {
        // W1 is [128][256]; half m gives rows of 128 floats (32 float4)
        const float4* W14 = (const float4*)W1;
        #pragma unroll
        for (int it = 0; it < 16; ++it) {
            int idx = tid + 256 * it;
            int t = idx >> 5, kc = idx & 31;
            *(float4*)&Ws[t * 132 + kc * 4] = W14[t * 64 + m * 32 + kc];
        }
    } else {
        // Ws[t][k] = Wb[k][t] (transpose load, coalesced gmem reads)
        for (int it = 0; it < 64; ++it) {
            int idx = tid + 256 * it;
            int k = idx >> 7, t = idx & 127;
            Ws[t * 132 + k] = Wb[k * H + t];
        }
    }
    {
        const float4* X4 = (const float4*)X;
        #pragma unroll
        for (int it = 0; it < 2; ++it) {
            int idx = tid + 256 * it;
            int g = idx >> 5, kc = idx & 31;
            Xs4[g * 32 + kc] = X4[(g0 + g) * 32 + kc];
        }
    }
    __syncthreads();

    int tq = tid & 31;   // t quad: t = tq*4 .. tq*4+3
    int gp = tid >> 5;   // gene pair: genes g0 + gp*2, +1

    float acc0[4] = {0.f, 0.f, 0.f, 0.f};
    float acc1[4] = {0.f, 0.f, 0.f, 0.f};
    #pragma unroll 4
    for (int k4 = 0; k4 < 32; ++k4) {
        float4 x0 = Xs4[(gp * 2) * 32 + k4];
        float4 x1 = Xs4[(gp * 2 + 1) * 32 + k4];
        #pragma unroll
        for (int q = 0; q < 4; ++q) {
            float4 w = *(const float4*)&Ws[(tq * 4 + q) * 132 + k4 * 4];
            acc0[q] = fmaf(x0.x, w.x, fmaf(x0.y, w.y, fmaf(x0.z, w.z, fmaf(x0.w, w.w, acc0[q]))));
            acc1[q] = fmaf(x1.x, w.x, fmaf(x1.y, w.y, fmaf(x1.z, w.z, fmaf(x1.w, w.w, acc1[q]))));
        }
    }

    int ga = g0 + gp * 2, gb = ga + 1;
    #pragma unroll
    for (int q = 0; q < 4; ++q) {
        int t = tq * 4 + q;
        float v0 = acc0[q], v1 = acc1[q];
        if (m == 0) {
            float bv = b1[t];
            v0 += bv; v1 += bv;
            *(float2*)&g_AiT_dup[t * 2 * NG + 2 * ga] = make_float2(v0, v0);
            *(float2*)&g_AiT_dup[t * 2 * NG + 2 * gb] = make_float2(v1, v1);
        } else if (m == 1) {
            g_BjT[t * NG + ga] = v0;
            g_BjT[t * NG + gb] = v1;
        } else {
            *(float2*)&g_YT_dup[t * 2 * NG + 2 * ga] = make_float2(v0, v0);
            *(float2*)&g_YT_dup[t * 2 * NG + 2 * gb] = make_float2(v1, v1);
        }
    }

    if (m == 1) {
        // also emit X^T (reads from Xs tile already in smem)
        #pragma unroll
        for (int it = 0; it < 8; ++it) {
            int idx = tid + 256 * it;
            int k = idx >> 4, g = idx & 15;
            g_XT[k * NG + g0 + g] = Xs[g * H + k];
        }
    }
}

// 64x64 pair tile per block, grid 12x12 (one wave on 148 SMs).
// Per thread: 4 i x 4 j outputs, j packed in f32x2 pairs.
__global__ __launch_bounds__(256, 1)
void pair_kernel(const float* __restrict__ W2, const float* __restrict__ b2,
                 const float* __restrict__ bb, float* __restrict__ out) {
    extern __shared__ float sm[];
    float* AsD = sm;                 // [128][128] dup'd Ai tile (64 genes x2)
    float* YsD = AsD + 128 * 128;    // [128][128] dup'd Y tile
    float* Bs  = YsD + 128 * 128;    // [128][64]
    float* Xs  = Bs + 128 * 64;      // [128][64]
    float* wdd = Xs + 128 * 64;      // [128][4] = (w0-w1, w0-w1, w0-w2, w0-w2)

    int tid = threadIdx.x;
    int bi = blockIdx.y, bj = blockIdx.x;

    const float4* A4 = (const float4*)g_AiT_dup;  // row = 384 float4
    const float4* Y4 = (const float4*)g_YT_dup;
    const float4* B4 = (const float4*)g_BjT;      // row = 192 float4
    const float4* X4 = (const float4*)g_XT;
    float4* AsD4 = (float4*)AsD;
    float4* YsD4 = (float4*)YsD;
    float4* Bs4  = (float4*)Bs;
    float4* Xs4  = (float4*)Xs;

    #pragma unroll
    for (int it = 0; it < 16; ++it) {           // 4096 float4 each
        int idx = tid + 256 * it;
        int k = idx >> 5, c = idx & 31;
        AsD4[idx] = A4[k * 384 + bi * 32 + c];
        YsD4[idx] = Y4[k * 384 + bi * 32 + c];
    }
    #pragma unroll
    for (int it = 0; it < 8; ++it) {            // 2048 float4 each (FIX: was 4)
        int idx = tid + 256 * it;
        int k = idx >> 4, c = idx & 15;
        Bs4[idx] = B4[k * 192 + bj * 16 + c];
        Xs4[idx] = X4[k * 192 + bj * 16 + c];
    }
    if (tid < H) {
        float w0 = W2[tid], w1 = W2[H + tid], w2v = W2[2 * H + tid];
        ((float4*)wdd)[tid] = make_float4(w0 - w1, w0 - w1, w0 - w2v, w0 - w2v);
    }
    __syncthreads();

    int tx = tid & 15, ty = tid >> 4;

    const ulonglong2* AsL = (const ulonglong2*)AsD;  // row = 32 ull2
    const ulonglong2* YsL = (const ulonglong2*)YsD;
    const ulonglong2* BsL = (const ulonglong2*)Bs;   // row = 16 ull2
    const ulonglong2* XsL = (const ulonglong2*)Xs;
    const ulonglong2* WdL = (const ulonglong2*)wdd;

    ull a01[8], a02[8], aaf[8];
    #pragma unroll
    for (int r = 0; r < 8; ++r) { a01[r] = 0ULL; a02[r] = 0ULL; aaf[r] = 0ULL; }

    #pragma unroll 2
    for (int k = 0; k < H; ++k) {
        ulonglong2 ad0 = AsL[k * 32 + ty * 2];
        ulonglong2 ad1 = AsL[k * 32 + ty * 2 + 1];
        ulonglong2 yd0 = YsL[k * 32 + ty * 2];
        ulonglong2 yd1 = YsL[k * 32 + ty * 2 + 1];
        ulonglong2 bq  = BsL[k * 16 + tx];
        ulonglong2 xq  = XsL[k * 16 + tx];
        ulonglong2 wq  = WdL[k];

        ull a2[4] = {ad0.x, ad0.y, ad1.x, ad1.y};
        ull y2[4] = {yd0.x, yd0.y, yd1.x, yd1.y};
        ull bv[2] = {bq.x, bq.y};
        ull xv[2] = {xq.x, xq.y};

        #pragma unroll
        for (int p = 0; p < 4; ++p) {
            #pragma unroll
            for (int qp = 0; qp < 2; ++qp) {
                int r = p * 2 + qp;
                ull h = relu2_add(a2[p], bv[qp]);
                fma2(a01[r], h, wq.x);          // (l0-l1) accumulator, 2 lanes
                fma2(a02[r], h, wq.y);          // (l0-l2) accumulator, 2 lanes
                fma2(aaf[r], y2[p], xv[qp]);    // bilinear affinity, 2 lanes
            }
        }
    }

    float db01 = b2[0] - b2[1];
    float db02 = b2[0] - b2[2];
    float bbv  = bb[0];

    #pragma unroll
    for (int p = 0; p < 4; ++p) {
        int gi = bi * 64 + ty * 4 + p;
        float ov[4];
        #pragma unroll
        for (int qp = 0; qp < 2; ++qp) {
            int r = p * 2 + qp;
            #pragma unroll
            for (int hhalf = 0; hhalf < 2; ++hhalf) {
                float c01 = __uint_as_float((unsigned)(hhalf ? (a01[r] >> 32) : a01[r]));
                float c02 = __uint_as_float((unsigned)(hhalf ? (a02[r] >> 32) : a02[r]));
                float caf = __uint_as_float((unsigned)(hhalf ? (aaf[r] >> 32) : aaf[r]));
                float d01 = c01 + db01;  // l0 - l1
                float d02 = c02 + db02;  // l0 - l2
                float af  = caf + bbv;
                // argmax first-occurrence: cls0 <=> d01>=0 && d02>=0 ;
                // cls2 <=> d02<0 && d02<d01
                float s = (d01 >= 0.f && d02 >= 0.f) ? 1.f
                        : ((d02 < 0.f && d02 < d01) ? -1.f : 0.f);
                int q = qp * 2 + hhalf;
                int gj = bj * 64 + tx * 4 + q;
                ov[q] = (gi == gj) ? 0.f : s * af;
            }
        }
        float4 o; o.x = ov[0]; o.y = ov[1]; o.z = ov[2]; o.w = ov[3];
        *(float4*)&out[gi * NG + bj * 64 + tx * 4] = o;
    }
}

extern "C" void kernel_launch(void* const* d_in, const int* in_sizes, int n_in,
                              void* d_out, int out_size) {
    const float* X  = (const float*)d_in[0];
    const float* W1 = (const float*)d_in[1];
    const float* b1 = (const float*)d_in[2];
    const float* W2 = (const float*)d_in[3];
    const float* b2 = (const float*)d_in[4];
    const float* Wb = (const float*)d_in[5];
    const float* bb = (const float*)d_in[6];
    float* out = (float*)d_out;

    size_t psmem = (size_t)(128 * 132 + 16 * 128) * sizeof(float);
    cudaFuncSetAttribute(prep_gemm, cudaFuncAttributeMaxDynamicSharedMemorySize,
                         (int)psmem);
    size_t smem = (size_t)(2 * 128 * 128 + 2 * 128 * 64 + 128 * 4) * sizeof(float);
    cudaFuncSetAttribute(pair_kernel, cudaFuncAttributeMaxDynamicSharedMemorySize,
                         (int)smem);

    prep_gemm<<<dim3(48, 3), 256, psmem>>>(X, W1, b1, Wb);
    pair_kernel<<<dim3(12, 12), 256, smem>>>(W2, b2, bb, out);
}